// round 8
// baseline (speedup 1.0000x reference)
#include <cuda_runtime.h>
#include <cuda_fp16.h>
#include <cstdint>
#include <math.h>

#define NDIM 4096

// ---------------- device scratch (no allocs allowed) ------------------------
__device__ float  g_sq[NDIM];
__device__ __half g_xh    [(size_t)NDIM * NDIM];   // x  fp16 [B,F]
__device__ __half g_xth   [(size_t)NDIM * NDIM];   // x^T fp16 [F,B]
__device__ __half g_wouth [(size_t)NDIM * NDIM];   // W_out fp16 [OUT,F]
__device__ __half g_gramh [(size_t)NDIM * NDIM];   // gram fp16
__device__ __half g_mixedh[(size_t)NDIM * NDIM];   // mixed fp16

// ---------------- helpers ---------------------------------------------------
__device__ __forceinline__ uint32_t smem_u32(const void* p) {
    uint32_t a;
    asm("{ .reg .u64 t; cvta.to.shared.u64 t, %1; cvt.u32.u64 %0, t; }"
        : "=r"(a) : "l"(p));
    return a;
}
__device__ __forceinline__ void cp16(uint32_t dst, const void* src) {
    asm volatile("cp.async.cg.shared.global [%0], [%1], 16;"
                 :: "r"(dst), "l"(src) : "memory");
}
__device__ __forceinline__ void cp_commit() {
    asm volatile("cp.async.commit_group;" ::: "memory");
}
__device__ __forceinline__ void cp_wait2() {
    asm volatile("cp.async.wait_group 2;" ::: "memory");
}
__device__ __forceinline__ uint32_t swz128(uint32_t off) {
    return off ^ ((off >> 3) & 0x70);          // SW128, 128B rows
}
__device__ __forceinline__ void ldsm4(uint32_t& r0, uint32_t& r1,
                                      uint32_t& r2, uint32_t& r3, uint32_t a) {
    asm volatile("ldmatrix.sync.aligned.m8n8.x4.shared.b16 {%0,%1,%2,%3}, [%4];"
                 : "=r"(r0), "=r"(r1), "=r"(r2), "=r"(r3) : "r"(a));
}
__device__ __forceinline__ void mma16816(float* c, const uint32_t* a,
                                         const uint32_t* b) {
    asm volatile(
        "mma.sync.aligned.m16n8k16.row.col.f32.f16.f16.f32 "
        "{%0,%1,%2,%3}, {%4,%5,%6,%7}, {%8,%9}, {%0,%1,%2,%3};"
        : "+f"(c[0]), "+f"(c[1]), "+f"(c[2]), "+f"(c[3])
        : "r"(a[0]), "r"(a[1]), "r"(a[2]), "r"(a[3]), "r"(b[0]), "r"(b[1]));
}

// ---------------- GEMM config ----------------------------------------------
constexpr int BM = 128, BN = 256, BK = 64;     // BK halves = 128 B rows (SW128)
constexpr int NITER = NDIM / BK;               // 64
constexpr int A_BYTES = BM * BK * 2;           // 16384
constexpr int B_BYTES = BN * BK * 2;           // 32768
constexpr int STAGE_BYTES = A_BYTES + B_BYTES; // 49152
constexpr int SMEM_TOTAL = 4 * STAGE_BYTES;    // 196608

// MODE 0: S = x x^T + dist/exp -> g_gramh
// MODE 1: mixed = gram @ x (B = x^T)   -> g_mixedh
// MODE 2: out = mixed @ W_out^T + b    -> Cext (fp32)
template <int MODE>
__global__ void __launch_bounds__(512)
hmma_gemm(const float* __restrict__ aux, float* __restrict__ Cext)
{
    extern __shared__ __align__(1024) char smem[];
    const uint32_t sb = smem_u32(smem);

    const int tid = threadIdx.x, wid = tid >> 5, lane = tid & 31;
    const int bm = blockIdx.y * BM, bn = blockIdx.x * BN;
    const int wm = (wid >> 3) * 64;      // 2 warps along M
    const int wn = (wid & 7) * 32;       // 8 warps along N

    const __half* Ag = (MODE == 0) ? g_xh : (MODE == 1) ? g_gramh : g_mixedh;
    const __half* Bg = (MODE == 0) ? g_xh : (MODE == 1) ? g_xth   : g_wouth;

    // cp.async mapping: A = 1024 16B chunks (2/thread), B = 2048 (4/thread)
    const int raA0 = (tid)        >> 3, caA0 = (tid)        & 7;
    const int raA1 = (tid + 512)  >> 3, caA1 = (tid + 512)  & 7;
    const __half* gA0 = Ag + (size_t)(bm + raA0) * NDIM + caA0 * 8;
    const __half* gA1 = Ag + (size_t)(bm + raA1) * NDIM + caA1 * 8;
    const uint32_t sA0 = swz128(raA0 * 128 + caA0 * 16);
    const uint32_t sA1 = swz128(raA1 * 128 + caA1 * 16);

    const __half* gB[4];
    uint32_t sB[4];
#pragma unroll
    for (int t = 0; t < 4; t++) {
        int ch = tid + t * 512;
        int r = ch >> 3, c = ch & 7;
        gB[t] = Bg + (size_t)(bn + r) * NDIM + c * 8;
        sB[t] = swz128(r * 128 + c * 16);
    }

    // ldmatrix lane offsets (bytes, pre-swizzle), 128B rows.
    // The swizzle must be applied to the FULL offset including ks*32:
    // swz128 XORs row bits into bits 4-6, so adding ks*32 after swizzling
    // can carry into bit 7 (wrong row / OOB) — that was the R6/R7 fault.
    const uint32_t aRB = (uint32_t)(wm + (lane & 15)) * 128 + (lane >> 4) * 16;
    const uint32_t bRB = (uint32_t)(wn + (lane & 7) + ((lane >> 4) << 3)) * 128 +
                         ((lane >> 3) & 1) * 16;

    float acc[4][4][4];
#pragma unroll
    for (int i = 0; i < 4; i++)
#pragma unroll
        for (int j = 0; j < 4; j++)
#pragma unroll
            for (int q = 0; q < 4; q++) acc[i][j][q] = 0.f;

    // double-buffered fragments
    uint32_t af[2][4][4], bf[2][4][2];

    auto load_frags = [&](int buf, uint32_t abase, int ks) {
        const uint32_t bbase = abase + A_BYTES;
#pragma unroll
        for (int mf = 0; mf < 4; mf++)
            ldsm4(af[buf][mf][0], af[buf][mf][1], af[buf][mf][2], af[buf][mf][3],
                  abase + swz128(aRB + mf * 2048 + ks * 32));
#pragma unroll
        for (int nf2 = 0; nf2 < 2; nf2++) {
            uint32_t r0, r1, r2, r3;
            // B stored [N,K]: non-trans ldmatrix = correct mma B fragment
            ldsm4(r0, r1, r2, r3,
                  bbase + swz128(bRB + nf2 * 2048 + ks * 32));
            bf[buf][2 * nf2][0] = r0;     bf[buf][2 * nf2][1] = r1;
            bf[buf][2 * nf2 + 1][0] = r2; bf[buf][2 * nf2 + 1][1] = r3;
        }
    };
    auto mma_all = [&](int buf) {
#pragma unroll
        for (int mf = 0; mf < 4; mf++)
#pragma unroll
            for (int nf = 0; nf < 4; nf++)
                mma16816(acc[mf][nf], af[buf][mf], bf[buf][nf]);
    };

    // prologue: stages 0..2
#pragma unroll
    for (int t = 0; t < 3; t++) {
        const uint32_t base = sb + t * STAGE_BYTES;
        const int kt = t * BK;
        cp16(base + sA0, gA0 + kt);
        cp16(base + sA1, gA1 + kt);
#pragma unroll
        for (int q = 0; q < 4; q++)
            cp16(base + A_BYTES + sB[q], gB[q] + kt);
        cp_commit();
    }

    cp_wait2();
    __syncthreads();
    load_frags(0, sb /*stage 0*/, 0);

    for (int it = 0; it < NITER; ++it) {
        const uint32_t abase = sb + (it & 3) * STAGE_BYTES;

        // issue next-stage loads (stage it+3) right away
        const int nt = it + 3;
        if (nt < NITER) {
            const uint32_t base = sb + (nt & 3) * STAGE_BYTES;
            const int kt = nt * BK;
            cp16(base + sA0, gA0 + kt);
            cp16(base + sA1, gA1 + kt);
#pragma unroll
            for (int q = 0; q < 4; q++)
                cp16(base + A_BYTES + sB[q], gB[q] + kt);
        }
        cp_commit();

        // pipelined ks loop: load ks+1 while issuing MMAs of ks
#pragma unroll
        for (int ks = 0; ks < 4; ks++) {
            if (ks < 3)
                load_frags((ks + 1) & 1, abase, ks + 1);
            mma_all(ks & 1);
        }

        // advance to next stage: barrier, then preload its ks=0 fragments
        if (it + 1 < NITER) {
            cp_wait2();
            __syncthreads();
            load_frags(0, sb + ((it + 1) & 3) * STAGE_BYTES, 0);
        }
    }

    // ---------------- epilogue (register accumulators) ----------------------
    const int rb = bm + wm + (lane >> 2);
    const int cb = bn + wn + (lane & 3) * 2;

    if (MODE == 0) {
        float2 sqc[4];
#pragma unroll
        for (int nf = 0; nf < 4; nf++)
            sqc[nf] = *reinterpret_cast<const float2*>(&g_sq[cb + nf * 8]);
#pragma unroll
        for (int mf = 0; mf < 4; mf++)
#pragma unroll
            for (int rs = 0; rs < 2; rs++) {
                const int row = rb + mf * 16 + rs * 8;
                const float sqi = g_sq[row];
                const float* wr = aux + (size_t)row * NDIM;
                __half* orow = g_gramh + (size_t)row * NDIM;
#pragma unroll
                for (int nf = 0; nf < 4; nf++) {
                    const int col = cb + nf * 8;
                    float2 w2 = *reinterpret_cast<const float2*>(&wr[col]);
                    float s0 = acc[mf][nf][rs * 2 + 0];
                    float s1 = acc[mf][nf][rs * 2 + 1];
                    float d0 = sqrtf(fmaxf(sqi + sqc[nf].x - 2.f * s0, 0.f));
                    float d1 = sqrtf(fmaxf(sqi + sqc[nf].y - 2.f * s1, 0.f));
                    __half2 h = __floats2half2_rn(__expf(-fabsf(w2.x) * d0),
                                                  __expf(-fabsf(w2.y) * d1));
                    *reinterpret_cast<__half2*>(&orow[col]) = h;
                }
            }
    } else if (MODE == 1) {
#pragma unroll
        for (int mf = 0; mf < 4; mf++)
#pragma unroll
            for (int rs = 0; rs < 2; rs++) {
                const int row = rb + mf * 16 + rs * 8;
                __half* orow = g_mixedh + (size_t)row * NDIM;
#pragma unroll
                for (int nf = 0; nf < 4; nf++) {
                    __half2 h = __floats2half2_rn(acc[mf][nf][rs * 2 + 0],
                                                  acc[mf][nf][rs * 2 + 1]);
                    *reinterpret_cast<__half2*>(&orow[cb + nf * 8]) = h;
                }
            }
    } else {
        float2 bias2[4];
#pragma unroll
        for (int nf = 0; nf < 4; nf++)
            bias2[nf] = *reinterpret_cast<const float2*>(&aux[cb + nf * 8]);
#pragma unroll
        for (int mf = 0; mf < 4; mf++)
#pragma unroll
            for (int rs = 0; rs < 2; rs++) {
                const int row = rb + mf * 16 + rs * 8;
                float* orow = Cext + (size_t)row * NDIM;
#pragma unroll
                for (int nf = 0; nf < 4; nf++) {
                    float2 v;
                    v.x = acc[mf][nf][rs * 2 + 0] + bias2[nf].x;
                    v.y = acc[mf][nf][rs * 2 + 1] + bias2[nf].y;
                    *reinterpret_cast<float2*>(&orow[cb + nf * 8]) = v;
                }
            }
    }
}

// ---------------- prep kernels ---------------------------------------------
__global__ void rownorm_kernel(const float* __restrict__ x) {
    const int row = blockIdx.x;
    const float4* xr = reinterpret_cast<const float4*>(x + (size_t)row * NDIM);
    float s = 0.f;
    for (int i = threadIdx.x; i < NDIM / 4; i += blockDim.x) {
        float4 v = xr[i];
        s += v.x * v.x + v.y * v.y + v.z * v.z + v.w * v.w;
    }
    __shared__ float red[256];
    red[threadIdx.x] = s;
    __syncthreads();
    for (int off = 128; off > 0; off >>= 1) {
        if (threadIdx.x < off) red[threadIdx.x] += red[threadIdx.x + off];
        __syncthreads();
    }
    if (threadIdx.x == 0) g_sq[row] = red[0];
}

// fused: x -> g_xh (fp16) and g_xth (fp16 transpose), one read of x
__global__ void prep_x_kernel(const float* __restrict__ src) {
    __shared__ float t[32][33];
    const int bx = blockIdx.x * 32, by = blockIdx.y * 32;
    const int tx = threadIdx.x, ty = threadIdx.y;   // (32, 8)
#pragma unroll
    for (int j = 0; j < 32; j += 8) {
        float v = src[(size_t)(by + ty + j) * NDIM + bx + tx];
        t[ty + j][tx] = v;
        g_xh[(size_t)(by + ty + j) * NDIM + bx + tx] = __float2half(v);
    }
    __syncthreads();
#pragma unroll
    for (int j = 0; j < 32; j += 8)
        g_xth[(size_t)(bx + ty + j) * NDIM + by + tx] = __float2half(t[tx][ty + j]);
}

__global__ void conv_wout_kernel(const float* __restrict__ src) {
    size_t i = ((size_t)blockIdx.x * blockDim.x + threadIdx.x) * 8;
    const float4* s = reinterpret_cast<const float4*>(src + i);
    float4 a = s[0], b = s[1];
    __half2 h0 = __floats2half2_rn(a.x, a.y);
    __half2 h1 = __floats2half2_rn(a.z, a.w);
    __half2 h2 = __floats2half2_rn(b.x, b.y);
    __half2 h3 = __floats2half2_rn(b.z, b.w);
    uint4 o;
    o.x = *reinterpret_cast<uint32_t*>(&h0);
    o.y = *reinterpret_cast<uint32_t*>(&h1);
    o.z = *reinterpret_cast<uint32_t*>(&h2);
    o.w = *reinterpret_cast<uint32_t*>(&h3);
    *reinterpret_cast<uint4*>(g_wouth + i) = o;
}

// ---------------------------------------------------------------------------
extern "C" void kernel_launch(void* const* d_in, const int* in_sizes, int n_in,
                              void* d_out, int out_size)
{
    const float* x     = (const float*)d_in[0];
    const float* W_rbf = (const float*)d_in[1];
    const float* W_out = (const float*)d_in[2];
    const float* b_out = (const float*)d_in[3];
    float* out = (float*)d_out;

    static bool attr_done = false;
    if (!attr_done) {
        cudaFuncSetAttribute(hmma_gemm<0>, cudaFuncAttributeMaxDynamicSharedMemorySize, SMEM_TOTAL);
        cudaFuncSetAttribute(hmma_gemm<1>, cudaFuncAttributeMaxDynamicSharedMemorySize, SMEM_TOTAL);
        cudaFuncSetAttribute(hmma_gemm<2>, cudaFuncAttributeMaxDynamicSharedMemorySize, SMEM_TOTAL);
        attr_done = true;
    }

    rownorm_kernel<<<NDIM, 256>>>(x);
    prep_x_kernel<<<dim3(128, 128), dim3(32, 8)>>>(x);
    conv_wout_kernel<<<8192, 256>>>(W_out);

    dim3 grid(NDIM / BN, NDIM / BM);   // 16 x 32
    hmma_gemm<0><<<grid, 512, SMEM_TOTAL>>>(W_rbf, nullptr);
    hmma_gemm<1><<<grid, 512, SMEM_TOTAL>>>(nullptr, nullptr);
    hmma_gemm<2><<<grid, 512, SMEM_TOTAL>>>(b_out, out);
}

// round 9
// speedup vs baseline: 1.2703x; 1.2703x over previous
#include <cuda_runtime.h>
#include <cuda_fp16.h>
#include <cstdint>
#include <math.h>

#define NDIM 4096

// ---------------- device scratch (no allocs allowed) ------------------------
__device__ float  g_sq[NDIM];
__device__ __half g_xh    [(size_t)NDIM * NDIM];   // x  fp16 [B,F]
__device__ __half g_xth   [(size_t)NDIM * NDIM];   // x^T fp16 [F,B]
__device__ __half g_wouth [(size_t)NDIM * NDIM];   // W_out fp16 [OUT,F]
__device__ __half g_gramh [(size_t)NDIM * NDIM];   // gram fp16
__device__ __half g_mixedh[(size_t)NDIM * NDIM];   // mixed fp16

// ---------------- helpers ---------------------------------------------------
__device__ __forceinline__ uint32_t smem_u32(const void* p) {
    uint32_t a;
    asm("{ .reg .u64 t; cvta.to.shared.u64 t, %1; cvt.u32.u64 %0, t; }"
        : "=r"(a) : "l"(p));
    return a;
}
__device__ __forceinline__ void cp16(uint32_t dst, const void* src) {
    asm volatile("cp.async.cg.shared.global [%0], [%1], 16;"
                 :: "r"(dst), "l"(src) : "memory");
}
__device__ __forceinline__ void cp_commit() {
    asm volatile("cp.async.commit_group;" ::: "memory");
}
__device__ __forceinline__ void cp_wait1() {
    asm volatile("cp.async.wait_group 1;" ::: "memory");
}
__device__ __forceinline__ uint32_t swz128(uint32_t off) {
    return off ^ ((off >> 3) & 0x70);          // SW128, 128B rows
}
__device__ __forceinline__ void ldsm4(uint32_t& r0, uint32_t& r1,
                                      uint32_t& r2, uint32_t& r3, uint32_t a) {
    asm volatile("ldmatrix.sync.aligned.m8n8.x4.shared.b16 {%0,%1,%2,%3}, [%4];"
                 : "=r"(r0), "=r"(r1), "=r"(r2), "=r"(r3) : "r"(a));
}
__device__ __forceinline__ void mma16816(float* c, const uint32_t* a,
                                         const uint32_t* b) {
    asm volatile(
        "mma.sync.aligned.m16n8k16.row.col.f32.f16.f16.f32 "
        "{%0,%1,%2,%3}, {%4,%5,%6,%7}, {%8,%9}, {%0,%1,%2,%3};"
        : "+f"(c[0]), "+f"(c[1]), "+f"(c[2]), "+f"(c[3])
        : "r"(a[0]), "r"(a[1]), "r"(a[2]), "r"(a[3]), "r"(b[0]), "r"(b[1]));
}

// ---------------- GEMM config ----------------------------------------------
// 256 threads/CTA, 2 CTAs/SM (independent barriers keep the tensor pipe fed
// while the sibling CTA syncs). Mainloop structure = proven R5 (no register
// fragment double-buffering — that spilled at the 128-reg cap).
constexpr int BM = 128, BN = 128, BK = 64;     // BK halves = 128 B rows (SW128)
constexpr int NITER = NDIM / BK;               // 64
constexpr int A_BYTES = BM * BK * 2;           // 16384
constexpr int B_BYTES = BN * BK * 2;           // 16384
constexpr int STAGE_BYTES = A_BYTES + B_BYTES; // 32768
constexpr int NSTAGE = 3;
constexpr int SMEM_TOTAL = NSTAGE * STAGE_BYTES;   // 98304 (x2 CTAs = 192K/SM)

// MODE 0: S = x x^T + dist/exp -> g_gramh
// MODE 1: mixed = gram @ x (B = x^T)   -> g_mixedh
// MODE 2: out = mixed @ W_out^T + b    -> Cext (fp32)
template <int MODE>
__global__ void __launch_bounds__(256, 2)
hmma_gemm(const float* __restrict__ aux, float* __restrict__ Cext)
{
    extern __shared__ __align__(1024) char smem[];
    const uint32_t sb = smem_u32(smem);

    const int tid = threadIdx.x, wid = tid >> 5, lane = tid & 31;
    const int bm = blockIdx.y * BM, bn = blockIdx.x * BN;
    const int wm = (wid >> 2) * 64;      // 2 warps along M
    const int wn = (wid & 3) * 32;       // 4 warps along N

    const __half* Ag = (MODE == 0) ? g_xh : (MODE == 1) ? g_gramh : g_mixedh;
    const __half* Bg = (MODE == 0) ? g_xh : (MODE == 1) ? g_xth   : g_wouth;

    // cp.async mapping: A and B each 1024 16B chunks -> 4 chunks/thread each
    const __half* gA[4];
    const __half* gB[4];
    uint32_t sA[4], sB[4];
#pragma unroll
    for (int t = 0; t < 4; t++) {
        int ch = tid + t * 256;
        int r = ch >> 3, c = ch & 7;
        gA[t] = Ag + (size_t)(bm + r) * NDIM + c * 8;
        gB[t] = Bg + (size_t)(bn + r) * NDIM + c * 8;
        sA[t] = swz128(r * 128 + c * 16);
        sB[t] = sA[t];
    }

    // ldmatrix lane offsets (bytes, pre-swizzle), 128B rows.
    // Swizzle is always applied to the FULL offset (incl. ks*32): swz128 maps
    // row bits into bits 4-6, so post-swizzle adds can carry into bit 7.
    const uint32_t aRB = (uint32_t)(wm + (lane & 15)) * 128 + (lane >> 4) * 16;
    const uint32_t bRB = (uint32_t)(wn + (lane & 7) + ((lane >> 4) << 3)) * 128 +
                         ((lane >> 3) & 1) * 16;

    float acc[4][4][4];
#pragma unroll
    for (int i = 0; i < 4; i++)
#pragma unroll
        for (int j = 0; j < 4; j++)
#pragma unroll
            for (int q = 0; q < 4; q++) acc[i][j][q] = 0.f;

    // prologue: stages 0,1
#pragma unroll
    for (int t = 0; t < 2; t++) {
        const uint32_t base = sb + t * STAGE_BYTES;
        const int kt = t * BK;
#pragma unroll
        for (int q = 0; q < 4; q++) {
            cp16(base + sA[q], gA[q] + kt);
            cp16(base + A_BYTES + sB[q], gB[q] + kt);
        }
        cp_commit();
    }

    for (int it = 0; it < NITER; ++it) {
        cp_wait1();
        __syncthreads();

        const int nt = it + 2;
        if (nt < NITER) {
            const uint32_t base = sb + (nt % 3) * STAGE_BYTES;
            const int kt = nt * BK;
#pragma unroll
            for (int q = 0; q < 4; q++) {
                cp16(base + sA[q], gA[q] + kt);
                cp16(base + A_BYTES + sB[q], gB[q] + kt);
            }
        }
        cp_commit();

        const uint32_t abase = sb + (it % 3) * STAGE_BYTES;
        const uint32_t bbase = abase + A_BYTES;

#pragma unroll
        for (int ks = 0; ks < 4; ks++) {
            uint32_t af[4][4], bf[4][2];
#pragma unroll
            for (int mf = 0; mf < 4; mf++)
                ldsm4(af[mf][0], af[mf][1], af[mf][2], af[mf][3],
                      abase + swz128(aRB + mf * 2048 + ks * 32));
#pragma unroll
            for (int nf2 = 0; nf2 < 2; nf2++) {
                uint32_t r0, r1, r2, r3;
                // B stored [N,K]: non-trans ldmatrix = correct mma B fragment
                ldsm4(r0, r1, r2, r3,
                      bbase + swz128(bRB + nf2 * 2048 + ks * 32));
                bf[2 * nf2][0] = r0;     bf[2 * nf2][1] = r1;
                bf[2 * nf2 + 1][0] = r2; bf[2 * nf2 + 1][1] = r3;
            }
#pragma unroll
            for (int mf = 0; mf < 4; mf++)
#pragma unroll
                for (int nf = 0; nf < 4; nf++)
                    mma16816(acc[mf][nf], af[mf], bf[nf]);
        }
    }

    // ---------------- epilogue (register accumulators) ----------------------
    const int rb = bm + wm + (lane >> 2);
    const int cb = bn + wn + (lane & 3) * 2;

    if (MODE == 0) {
        float2 sqc[4];
#pragma unroll
        for (int nf = 0; nf < 4; nf++)
            sqc[nf] = *reinterpret_cast<const float2*>(&g_sq[cb + nf * 8]);
#pragma unroll
        for (int mf = 0; mf < 4; mf++)
#pragma unroll
            for (int rs = 0; rs < 2; rs++) {
                const int row = rb + mf * 16 + rs * 8;
                const float sqi = g_sq[row];
                const float* wr = aux + (size_t)row * NDIM;
                __half* orow = g_gramh + (size_t)row * NDIM;
#pragma unroll
                for (int nf = 0; nf < 4; nf++) {
                    const int col = cb + nf * 8;
                    float2 w2 = *reinterpret_cast<const float2*>(&wr[col]);
                    float s0 = acc[mf][nf][rs * 2 + 0];
                    float s1 = acc[mf][nf][rs * 2 + 1];
                    float d0 = sqrtf(fmaxf(sqi + sqc[nf].x - 2.f * s0, 0.f));
                    float d1 = sqrtf(fmaxf(sqi + sqc[nf].y - 2.f * s1, 0.f));
                    __half2 h = __floats2half2_rn(__expf(-fabsf(w2.x) * d0),
                                                  __expf(-fabsf(w2.y) * d1));
                    *reinterpret_cast<__half2*>(&orow[col]) = h;
                }
            }
    } else if (MODE == 1) {
#pragma unroll
        for (int mf = 0; mf < 4; mf++)
#pragma unroll
            for (int rs = 0; rs < 2; rs++) {
                const int row = rb + mf * 16 + rs * 8;
                __half* orow = g_mixedh + (size_t)row * NDIM;
#pragma unroll
                for (int nf = 0; nf < 4; nf++) {
                    __half2 h = __floats2half2_rn(acc[mf][nf][rs * 2 + 0],
                                                  acc[mf][nf][rs * 2 + 1]);
                    *reinterpret_cast<__half2*>(&orow[cb + nf * 8]) = h;
                }
            }
    } else {
        float2 bias2[4];
#pragma unroll
        for (int nf = 0; nf < 4; nf++)
            bias2[nf] = *reinterpret_cast<const float2*>(&aux[cb + nf * 8]);
#pragma unroll
        for (int mf = 0; mf < 4; mf++)
#pragma unroll
            for (int rs = 0; rs < 2; rs++) {
                const int row = rb + mf * 16 + rs * 8;
                float* orow = Cext + (size_t)row * NDIM;
#pragma unroll
                for (int nf = 0; nf < 4; nf++) {
                    float2 v;
                    v.x = acc[mf][nf][rs * 2 + 0] + bias2[nf].x;
                    v.y = acc[mf][nf][rs * 2 + 1] + bias2[nf].y;
                    *reinterpret_cast<float2*>(&orow[cb + nf * 8]) = v;
                }
            }
    }
}

// ---------------- prep kernels ---------------------------------------------
__global__ void rownorm_kernel(const float* __restrict__ x) {
    const int row = blockIdx.x;
    const float4* xr = reinterpret_cast<const float4*>(x + (size_t)row * NDIM);
    float s = 0.f;
    for (int i = threadIdx.x; i < NDIM / 4; i += blockDim.x) {
        float4 v = xr[i];
        s += v.x * v.x + v.y * v.y + v.z * v.z + v.w * v.w;
    }
    __shared__ float red[256];
    red[threadIdx.x] = s;
    __syncthreads();
    for (int off = 128; off > 0; off >>= 1) {
        if (threadIdx.x < off) red[threadIdx.x] += red[threadIdx.x + off];
        __syncthreads();
    }
    if (threadIdx.x == 0) g_sq[row] = red[0];
}

// fused: x -> g_xh (fp16) and g_xth (fp16 transpose), one read of x
__global__ void prep_x_kernel(const float* __restrict__ src) {
    __shared__ float t[32][33];
    const int bx = blockIdx.x * 32, by = blockIdx.y * 32;
    const int tx = threadIdx.x, ty = threadIdx.y;   // (32, 8)
#pragma unroll
    for (int j = 0; j < 32; j += 8) {
        float v = src[(size_t)(by + ty + j) * NDIM + bx + tx];
        t[ty + j][tx] = v;
        g_xh[(size_t)(by + ty + j) * NDIM + bx + tx] = __float2half(v);
    }
    __syncthreads();
#pragma unroll
    for (int j = 0; j < 32; j += 8)
        g_xth[(size_t)(bx + ty + j) * NDIM + by + tx] = __float2half(t[tx][ty + j]);
}

__global__ void conv_wout_kernel(const float* __restrict__ src) {
    size_t i = ((size_t)blockIdx.x * blockDim.x + threadIdx.x) * 8;
    const float4* s = reinterpret_cast<const float4*>(src + i);
    float4 a = s[0], b = s[1];
    __half2 h0 = __floats2half2_rn(a.x, a.y);
    __half2 h1 = __floats2half2_rn(a.z, a.w);
    __half2 h2 = __floats2half2_rn(b.x, b.y);
    __half2 h3 = __floats2half2_rn(b.z, b.w);
    uint4 o;
    o.x = *reinterpret_cast<uint32_t*>(&h0);
    o.y = *reinterpret_cast<uint32_t*>(&h1);
    o.z = *reinterpret_cast<uint32_t*>(&h2);
    o.w = *reinterpret_cast<uint32_t*>(&h3);
    *reinterpret_cast<uint4*>(g_wouth + i) = o;
}

// ---------------------------------------------------------------------------
extern "C" void kernel_launch(void* const* d_in, const int* in_sizes, int n_in,
                              void* d_out, int out_size)
{
    const float* x     = (const float*)d_in[0];
    const float* W_rbf = (const float*)d_in[1];
    const float* W_out = (const float*)d_in[2];
    const float* b_out = (const float*)d_in[3];
    float* out = (float*)d_out;

    static bool attr_done = false;
    if (!attr_done) {
        cudaFuncSetAttribute(hmma_gemm<0>, cudaFuncAttributeMaxDynamicSharedMemorySize, SMEM_TOTAL);
        cudaFuncSetAttribute(hmma_gemm<1>, cudaFuncAttributeMaxDynamicSharedMemorySize, SMEM_TOTAL);
        cudaFuncSetAttribute(hmma_gemm<2>, cudaFuncAttributeMaxDynamicSharedMemorySize, SMEM_TOTAL);
        attr_done = true;
    }

    rownorm_kernel<<<NDIM, 256>>>(x);
    prep_x_kernel<<<dim3(128, 128), dim3(32, 8)>>>(x);
    conv_wout_kernel<<<8192, 256>>>(W_out);

    dim3 grid(NDIM / BN, NDIM / BM);   // 32 x 32
    hmma_gemm<0><<<grid, 256, SMEM_TOTAL>>>(W_rbf, nullptr);
    hmma_gemm<1><<<grid, 256, SMEM_TOTAL>>>(nullptr, nullptr);
    hmma_gemm<2><<<grid, 256, SMEM_TOTAL>>>(b_out, out);
}

// round 10
// speedup vs baseline: 1.4323x; 1.1276x over previous
#include <cuda_runtime.h>
#include <cuda_fp16.h>
#include <cstdint>
#include <math.h>

#define NDIM 4096

// ---------------- device scratch (no allocs allowed) ------------------------
__device__ float  g_sq[NDIM];
__device__ __half g_xh    [(size_t)NDIM * NDIM];   // x  fp16 [B,F]
__device__ __half g_xth   [(size_t)NDIM * NDIM];   // x^T fp16 [F,B]
__device__ __half g_wouth [(size_t)NDIM * NDIM];   // W_out fp16 [OUT,F]
__device__ __half g_gramh [(size_t)NDIM * NDIM];   // gram fp16
__device__ __half g_mixedh[(size_t)NDIM * NDIM];   // mixed fp16

// ---------------- helpers ---------------------------------------------------
__device__ __forceinline__ uint32_t smem_u32(const void* p) {
    uint32_t a;
    asm("{ .reg .u64 t; cvta.to.shared.u64 t, %1; cvt.u32.u64 %0, t; }"
        : "=r"(a) : "l"(p));
    return a;
}
__device__ __forceinline__ void cp16(uint32_t dst, const void* src) {
    asm volatile("cp.async.cg.shared.global [%0], [%1], 16;"
                 :: "r"(dst), "l"(src) : "memory");
}
__device__ __forceinline__ void cp_commit() {
    asm volatile("cp.async.commit_group;" ::: "memory");
}
__device__ __forceinline__ void cp_wait1() {
    asm volatile("cp.async.wait_group 1;" ::: "memory");
}
__device__ __forceinline__ uint32_t swz128(uint32_t off) {
    return off ^ ((off >> 3) & 0x70);          // SW128, 128B rows
}
__device__ __forceinline__ void ldsm4(uint32_t& r0, uint32_t& r1,
                                      uint32_t& r2, uint32_t& r3, uint32_t a) {
    asm volatile("ldmatrix.sync.aligned.m8n8.x4.shared.b16 {%0,%1,%2,%3}, [%4];"
                 : "=r"(r0), "=r"(r1), "=r"(r2), "=r"(r3) : "r"(a));
}
__device__ __forceinline__ void mma16816(float* c, const uint32_t* a,
                                         const uint32_t* b) {
    asm volatile(
        "mma.sync.aligned.m16n8k16.row.col.f32.f16.f16.f32 "
        "{%0,%1,%2,%3}, {%4,%5,%6,%7}, {%8,%9}, {%0,%1,%2,%3};"
        : "+f"(c[0]), "+f"(c[1]), "+f"(c[2]), "+f"(c[3])
        : "r"(a[0]), "r"(a[1]), "r"(a[2]), "r"(a[3]), "r"(b[0]), "r"(b[1]));
}

// ---------------- GEMM config ----------------------------------------------
constexpr int BM = 128, BN = 128, BK = 64;     // BK halves = 128 B rows (SW128)
constexpr int NITER = NDIM / BK;               // 64
constexpr int A_BYTES = BM * BK * 2;           // 16384
constexpr int B_BYTES = BN * BK * 2;           // 16384
constexpr int STAGE_BYTES = A_BYTES + B_BYTES; // 32768
constexpr int NSTAGE = 3;
constexpr int SMEM_TOTAL = NSTAGE * STAGE_BYTES;   // 98304 (x2 CTAs = 192K/SM)
constexpr int NTILE = NDIM / BM;               // 32
constexpr int TRI_BLOCKS = NTILE * (NTILE + 1) / 2;   // 528
constexpr int DPAD = 129;                      // smem_d row pad (floats)

// MODE 0: S = x x^T (upper-tri tiles only) + dist/exp -> g_gramh (+mirror)
// MODE 1: mixed = gram @ x (B = x^T)   -> g_mixedh
// MODE 2: out = mixed @ W_out^T + b    -> Cext (fp32)
template <int MODE>
__global__ void __launch_bounds__(256, 2)
hmma_gemm(const float* __restrict__ aux, float* __restrict__ Cext)
{
    extern __shared__ __align__(1024) char smem[];
    const uint32_t sb = smem_u32(smem);

    const int tid = threadIdx.x, wid = tid >> 5, lane = tid & 31;
    int bm, bn;
    if (MODE == 0) {
        // decode linear block id -> upper-triangular tile (i, j), j >= i
        int rem = blockIdx.x, i = 0;
        while (rem >= NTILE - i) { rem -= NTILE - i; i++; }
        bm = i * BM;
        bn = (i + rem) * BN;
    } else {
        bm = blockIdx.y * BM;
        bn = blockIdx.x * BN;
    }
    const int wm = (wid >> 2) * 64;      // 2 warps along M
    const int wn = (wid & 3) * 32;       // 4 warps along N

    const __half* Ag = (MODE == 0) ? g_xh : (MODE == 1) ? g_gramh : g_mixedh;
    const __half* Bg = (MODE == 0) ? g_xh : (MODE == 1) ? g_xth   : g_wouth;

    // cp.async mapping: A and B each 1024 16B chunks -> 4 chunks/thread each
    const __half* gA[4];
    const __half* gB[4];
    uint32_t sA[4], sB[4];
#pragma unroll
    for (int t = 0; t < 4; t++) {
        int ch = tid + t * 256;
        int r = ch >> 3, c = ch & 7;
        gA[t] = Ag + (size_t)(bm + r) * NDIM + c * 8;
        gB[t] = Bg + (size_t)(bn + r) * NDIM + c * 8;
        sA[t] = swz128(r * 128 + c * 16);
        sB[t] = sA[t];
    }

    // ldmatrix lane offsets (bytes, pre-swizzle), 128B rows.
    // Swizzle is always applied to the FULL offset (incl. ks*32).
    const uint32_t aRB = (uint32_t)(wm + (lane & 15)) * 128 + (lane >> 4) * 16;
    const uint32_t bRB = (uint32_t)(wn + (lane & 7) + ((lane >> 4) << 3)) * 128 +
                         ((lane >> 3) & 1) * 16;

    float acc[4][4][4];
#pragma unroll
    for (int i = 0; i < 4; i++)
#pragma unroll
        for (int j = 0; j < 4; j++)
#pragma unroll
            for (int q = 0; q < 4; q++) acc[i][j][q] = 0.f;

    // prologue: stages 0,1
#pragma unroll
    for (int t = 0; t < 2; t++) {
        const uint32_t base = sb + t * STAGE_BYTES;
        const int kt = t * BK;
#pragma unroll
        for (int q = 0; q < 4; q++) {
            cp16(base + sA[q], gA[q] + kt);
            cp16(base + A_BYTES + sB[q], gB[q] + kt);
        }
        cp_commit();
    }

    for (int it = 0; it < NITER; ++it) {
        cp_wait1();
        __syncthreads();

        const int nt = it + 2;
        if (nt < NITER) {
            const uint32_t base = sb + (nt % 3) * STAGE_BYTES;
            const int kt = nt * BK;
#pragma unroll
            for (int q = 0; q < 4; q++) {
                cp16(base + sA[q], gA[q] + kt);
                cp16(base + A_BYTES + sB[q], gB[q] + kt);
            }
        }
        cp_commit();

        const uint32_t abase = sb + (it % 3) * STAGE_BYTES;
        const uint32_t bbase = abase + A_BYTES;

#pragma unroll
        for (int ks = 0; ks < 4; ks++) {
            uint32_t af[4][4], bf[4][2];
#pragma unroll
            for (int mf = 0; mf < 4; mf++)
                ldsm4(af[mf][0], af[mf][1], af[mf][2], af[mf][3],
                      abase + swz128(aRB + mf * 2048 + ks * 32));
#pragma unroll
            for (int nf2 = 0; nf2 < 2; nf2++) {
                uint32_t r0, r1, r2, r3;
                // B stored [N,K]: non-trans ldmatrix = correct mma B fragment
                ldsm4(r0, r1, r2, r3,
                      bbase + swz128(bRB + nf2 * 2048 + ks * 32));
                bf[2 * nf2][0] = r0;     bf[2 * nf2][1] = r1;
                bf[2 * nf2 + 1][0] = r2; bf[2 * nf2 + 1][1] = r3;
            }
#pragma unroll
            for (int mf = 0; mf < 4; mf++)
#pragma unroll
                for (int nf = 0; nf < 4; nf++)
                    mma16816(acc[mf][nf], af[mf], bf[nf]);
        }
    }

    // ---------------- epilogue (register accumulators) ----------------------
    const int rb = bm + wm + (lane >> 2);
    const int cb = bn + wn + (lane & 3) * 2;

    if (MODE == 0) {
        const bool diag = (bm == bn);
        float* smem_d = reinterpret_cast<float*>(smem);   // reuse stage buffers
        __syncthreads();   // mainloop LDSM done before smem_d overwrites stages

        float2 sqc[4];
#pragma unroll
        for (int nf = 0; nf < 4; nf++)
            sqc[nf] = *reinterpret_cast<const float2*>(&g_sq[cb + nf * 8]);
#pragma unroll
        for (int mf = 0; mf < 4; mf++)
#pragma unroll
            for (int rs = 0; rs < 2; rs++) {
                const int row = rb + mf * 16 + rs * 8;
                const int row_l = row - bm;
                const float sqi = g_sq[row];
                const float* wr = aux + (size_t)row * NDIM;
                __half* orow = g_gramh + (size_t)row * NDIM;
#pragma unroll
                for (int nf = 0; nf < 4; nf++) {
                    const int col = cb + nf * 8;
                    const int col_l = col - bn;
                    float2 w2 = *reinterpret_cast<const float2*>(&wr[col]);
                    float s0 = acc[mf][nf][rs * 2 + 0];
                    float s1 = acc[mf][nf][rs * 2 + 1];
                    float d0 = sqrtf(fmaxf(sqi + sqc[nf].x - 2.f * s0, 0.f));
                    float d1 = sqrtf(fmaxf(sqi + sqc[nf].y - 2.f * s1, 0.f));
                    __half2 h = __floats2half2_rn(__expf(-fabsf(w2.x) * d0),
                                                  __expf(-fabsf(w2.y) * d1));
                    *reinterpret_cast<__half2*>(&orow[col]) = h;
                    if (!diag) {
                        smem_d[row_l * DPAD + col_l]     = d0;
                        smem_d[row_l * DPAD + col_l + 1] = d1;
                    }
                }
            }

        if (!diag) {
            __syncthreads();
            // mirror pass: write gram[bn+co][bm+ro] = exp(-|W[bn+co][bm+ro]|*d)
            // thread t: row co = t>>1, column half rhalf = (t&1)*64
            const int co = tid >> 1;
            const int rhalf = (tid & 1) * 64;
            const float* wrow = aux + (size_t)(bn + co) * NDIM + bm + rhalf;
            __half* grow = g_gramh + (size_t)(bn + co) * NDIM + bm + rhalf;
            __align__(16) __half hb[64];
#pragma unroll
            for (int u = 0; u < 64; u += 4) {
                float4 w4 = *reinterpret_cast<const float4*>(wrow + u);
                float dd0 = smem_d[(rhalf + u + 0) * DPAD + co];
                float dd1 = smem_d[(rhalf + u + 1) * DPAD + co];
                float dd2 = smem_d[(rhalf + u + 2) * DPAD + co];
                float dd3 = smem_d[(rhalf + u + 3) * DPAD + co];
                hb[u + 0] = __float2half(__expf(-fabsf(w4.x) * dd0));
                hb[u + 1] = __float2half(__expf(-fabsf(w4.y) * dd1));
                hb[u + 2] = __float2half(__expf(-fabsf(w4.z) * dd2));
                hb[u + 3] = __float2half(__expf(-fabsf(w4.w) * dd3));
            }
#pragma unroll
            for (int q = 0; q < 8; q++)
                reinterpret_cast<uint4*>(grow)[q] =
                    reinterpret_cast<uint4*>(hb)[q];
        }
    } else if (MODE == 1) {
#pragma unroll
        for (int mf = 0; mf < 4; mf++)
#pragma unroll
            for (int rs = 0; rs < 2; rs++) {
                const int row = rb + mf * 16 + rs * 8;
                __half* orow = g_mixedh + (size_t)row * NDIM;
#pragma unroll
                for (int nf = 0; nf < 4; nf++) {
                    __half2 h = __floats2half2_rn(acc[mf][nf][rs * 2 + 0],
                                                  acc[mf][nf][rs * 2 + 1]);
                    *reinterpret_cast<__half2*>(&orow[cb + nf * 8]) = h;
                }
            }
    } else {
        float2 bias2[4];
#pragma unroll
        for (int nf = 0; nf < 4; nf++)
            bias2[nf] = *reinterpret_cast<const float2*>(&aux[cb + nf * 8]);
#pragma unroll
        for (int mf = 0; mf < 4; mf++)
#pragma unroll
            for (int rs = 0; rs < 2; rs++) {
                const int row = rb + mf * 16 + rs * 8;
                float* orow = Cext + (size_t)row * NDIM;
#pragma unroll
                for (int nf = 0; nf < 4; nf++) {
                    float2 v;
                    v.x = acc[mf][nf][rs * 2 + 0] + bias2[nf].x;
                    v.y = acc[mf][nf][rs * 2 + 1] + bias2[nf].y;
                    *reinterpret_cast<float2*>(&orow[cb + nf * 8]) = v;
                }
            }
    }
}

// ---------------- prep kernels ---------------------------------------------
__global__ void rownorm_kernel(const float* __restrict__ x) {
    const int row = blockIdx.x;
    const float4* xr = reinterpret_cast<const float4*>(x + (size_t)row * NDIM);
    float s = 0.f;
    for (int i = threadIdx.x; i < NDIM / 4; i += blockDim.x) {
        float4 v = xr[i];
        s += v.x * v.x + v.y * v.y + v.z * v.z + v.w * v.w;
    }
    __shared__ float red[256];
    red[threadIdx.x] = s;
    __syncthreads();
    for (int off = 128; off > 0; off >>= 1) {
        if (threadIdx.x < off) red[threadIdx.x] += red[threadIdx.x + off];
        __syncthreads();
    }
    if (threadIdx.x == 0) g_sq[row] = red[0];
}

// fused: x -> g_xh (fp16) and g_xth (fp16 transpose), one read of x
__global__ void prep_x_kernel(const float* __restrict__ src) {
    __shared__ float t[32][33];
    const int bx = blockIdx.x * 32, by = blockIdx.y * 32;
    const int tx = threadIdx.x, ty = threadIdx.y;   // (32, 8)
#pragma unroll
    for (int j = 0; j < 32; j += 8) {
        float v = src[(size_t)(by + ty + j) * NDIM + bx + tx];
        t[ty + j][tx] = v;
        g_xh[(size_t)(by + ty + j) * NDIM + bx + tx] = __float2half(v);
    }
    __syncthreads();
#pragma unroll
    for (int j = 0; j < 32; j += 8)
        g_xth[(size_t)(bx + ty + j) * NDIM + by + tx] = __float2half(t[tx][ty + j]);
}

__global__ void conv_wout_kernel(const float* __restrict__ src) {
    size_t i = ((size_t)blockIdx.x * blockDim.x + threadIdx.x) * 8;
    const float4* s = reinterpret_cast<const float4*>(src + i);
    float4 a = s[0], b = s[1];
    __half2 h0 = __floats2half2_rn(a.x, a.y);
    __half2 h1 = __floats2half2_rn(a.z, a.w);
    __half2 h2 = __floats2half2_rn(b.x, b.y);
    __half2 h3 = __floats2half2_rn(b.z, b.w);
    uint4 o;
    o.x = *reinterpret_cast<uint32_t*>(&h0);
    o.y = *reinterpret_cast<uint32_t*>(&h1);
    o.z = *reinterpret_cast<uint32_t*>(&h2);
    o.w = *reinterpret_cast<uint32_t*>(&h3);
    *reinterpret_cast<uint4*>(g_wouth + i) = o;
}

// ---------------------------------------------------------------------------
extern "C" void kernel_launch(void* const* d_in, const int* in_sizes, int n_in,
                              void* d_out, int out_size)
{
    const float* x     = (const float*)d_in[0];
    const float* W_rbf = (const float*)d_in[1];
    const float* W_out = (const float*)d_in[2];
    const float* b_out = (const float*)d_in[3];
    float* out = (float*)d_out;

    static bool attr_done = false;
    if (!attr_done) {
        cudaFuncSetAttribute(hmma_gemm<0>, cudaFuncAttributeMaxDynamicSharedMemorySize, SMEM_TOTAL);
        cudaFuncSetAttribute(hmma_gemm<1>, cudaFuncAttributeMaxDynamicSharedMemorySize, SMEM_TOTAL);
        cudaFuncSetAttribute(hmma_gemm<2>, cudaFuncAttributeMaxDynamicSharedMemorySize, SMEM_TOTAL);
        attr_done = true;
    }

    rownorm_kernel<<<NDIM, 256>>>(x);
    prep_x_kernel<<<dim3(128, 128), dim3(32, 8)>>>(x);
    conv_wout_kernel<<<8192, 256>>>(W_out);

    dim3 grid(NDIM / BN, NDIM / BM);   // 32 x 32
    hmma_gemm<0><<<TRI_BLOCKS, 256, SMEM_TOTAL>>>(W_rbf, nullptr);
    hmma_gemm<1><<<grid, 256, SMEM_TOTAL>>>(nullptr, nullptr);
    hmma_gemm<2><<<grid, 256, SMEM_TOTAL>>>(b_out, out);
}